// round 16
// baseline (speedup 1.0000x reference)
#include <cuda_runtime.h>
#include <cuda_fp16.h>
#include <cstdint>

#define NB 8
#define CH 64
#define HH 256
#define WW 256
#define PP (HH*WW)   // 65536 pixels per batch

// fp16 scratch: 8-deep NHWC feature ring (64MB) + 2-deep NHWC intermediate.
__device__ __half g_fN[8][(size_t)PP * CH];
__device__ __half g_first[2][(size_t)PP * CH];

// Bin-sort state (computed once per replay from grid only).
__device__ int g_hist[NB][256];
__device__ int g_cur[NB][256];
__device__ int g_bstart[NB][257];
__device__ int g_sidx[NB][PP];

// ---------------------------------------------------------------------------
// Transpose one 64ch x 64px tile of batch n: fp32 NCHW -> fp16 NHWC.
// ---------------------------------------------------------------------------
__device__ __forceinline__ void transpose_tile(const float* __restrict__ feat,
                                               int n, int tile,
                                               float* __restrict__ sm /*64*65*/) {
    const int pbase = tile * 64;
    const int t = threadIdx.x;
    const float* src = feat + (size_t)n * CH * PP;

    const int px4 = (t & 15) * 4;
    const int c0  = t >> 4;
    #pragma unroll
    for (int i = 0; i < 4; i++) {
        const int c = c0 + i * 16;
        const float4 v = *(const float4*)(src + (size_t)c * PP + pbase + px4);
        sm[c * 65 + px4 + 0] = v.x;
        sm[c * 65 + px4 + 1] = v.y;
        sm[c * 65 + px4 + 2] = v.z;
        sm[c * 65 + px4 + 3] = v.w;
    }
    __syncthreads();

    __half* dst = g_fN[n & 7];
    const int c8  = t & 7;
    const int px0 = t >> 3;
    #pragma unroll
    for (int i = 0; i < 2; i++) {
        const int px = px0 + 32 * i;
        __half2 h[4];
        #pragma unroll
        for (int k = 0; k < 4; k++) {
            float2 f = make_float2(sm[(c8 * 8 + 2 * k) * 65 + px],
                                   sm[(c8 * 8 + 2 * k + 1) * 65 + px]);
            h[k] = __float22half2_rn(f);
        }
        ((uint4*)(dst + (size_t)(pbase + px) * 64))[c8] = *(uint4*)h;
    }
}

// ---------------------------------------------------------------------------
// Bilinear helpers (fp32 math; zeros padding folded into weights)
// ---------------------------------------------------------------------------
__device__ __forceinline__ void bl_setup(float gx, float gy,
                                         int& x0, int& y0, float& fx, float& fy) {
    float ix = ((gx + 1.0f) * (float)WW - 1.0f) * 0.5f;
    float iy = ((gy + 1.0f) * (float)HH - 1.0f) * 0.5f;
    float fx0 = floorf(ix);
    float fy0 = floorf(iy);
    fx = ix - fx0;
    fy = iy - fy0;
    x0 = (int)fx0;
    y0 = (int)fy0;
}

__device__ __forceinline__ void bl_weights(int x0, int y0, float fx, float fy,
                                           float* w /*4*/) {
    const float vx0 = (x0 >= 0) ? 1.0f : 0.0f;
    const float vx1 = (x0 + 1 < WW) ? 1.0f : 0.0f;
    const float vy0 = (y0 >= 0) ? 1.0f : 0.0f;
    const float vy1 = (y0 + 1 < HH) ? 1.0f : 0.0f;
    const float ax0 = (1.0f - fx) * vx0, ax1 = fx * vx1;
    const float ay0 = (1.0f - fy) * vy0, ay1 = fy * vy1;
    w[0] = ax0 * ay0; w[1] = ax1 * ay0; w[2] = ax0 * ay1; w[3] = ax1 * ay1;
}

__device__ __forceinline__ void accum(const uint4* v, const float* w,
                                      float* acc) {
    #pragma unroll
    for (int j = 0; j < 4; j++) {
        const __half2* h = (const __half2*)&v[j];
        #pragma unroll
        for (int k = 0; k < 4; k++) {
            float2 f = __half22float2(h[k]);
            acc[2 * k]     += f.x * w[j];
            acc[2 * k + 1] += f.y * w[j];
        }
    }
}

__device__ __forceinline__ void store_h8(__half* __restrict__ dst, int p, int c8,
                                         const float* acc) {
    __half2 h[4];
    #pragma unroll
    for (int k = 0; k < 4; k++)
        h[k] = __float22half2_rn(make_float2(acc[2 * k], acc[2 * k + 1]));
    ((uint4*)(dst + (size_t)p * 64))[c8] = *(uint4*)h;
}

__device__ __forceinline__ int pixel_bin(float2 g) {
    int x0, y0; float fx, fy;
    bl_setup(g.x, g.y, x0, y0, fx, fy);
    const int xc = min(max(x0, 0), WW - 1);
    const int yc = min(max(y0, 0), HH - 1);
    return (yc >> 4) * 16 + (xc >> 4);
}

// ---------------------------------------------------------------------------
// Pass1 bin-block: serve one bin's pixels from an smem-resident 17x17 region.
// sreg: 17*17 cells x 128B = 2312 uint4.
// ---------------------------------------------------------------------------
__device__ __forceinline__ void pass1_bin_block(const float* __restrict__ grid,
                                                int n, int bin,
                                                uint4* __restrict__ sreg) {
    const int t  = threadIdx.x;
    const int bx = bin & 15, by = bin >> 4;

    // Stream region into smem: coalesced 128B-per-cell loads.
    const uint4* src = (const uint4*)g_fN[n & 7];
    for (int idx = t; idx < 17 * 17 * 8; idx += 256) {
        const int cell = idx >> 3, ck = idx & 7;
        const int gy = min(by * 16 + cell / 17, HH - 1);
        const int gx = min(bx * 16 + cell % 17, WW - 1);
        sreg[idx] = src[(((gy << 8) + gx) << 3) + ck];
    }
    __syncthreads();

    const int c8 = t & 7;
    const int px = t >> 3;          // 0..31
    const int s  = g_bstart[n][bin];
    const int cnt = g_bstart[n][bin + 1] - s;
    __half* dst = g_first[n & 1];

    for (int base = 0; base < cnt; base += 32) {
        const int i = base + px;
        if (i < cnt) {
            const int p = g_sidx[n][s + i];
            const float2 g = ((const float2*)grid)[(size_t)n * PP + p];
            int x0, y0; float fx, fy;
            bl_setup(g.x, g.y, x0, y0, fx, fy);
            float w[4];
            bl_weights(x0, y0, fx, fy, w);

            const int sx0 = min(max(x0, 0), WW - 1) - bx * 16;
            const int sx1 = min(x0 + 1, WW - 1) - bx * 16;
            const int sy0 = min(max(y0, 0), HH - 1) - by * 16;
            const int sy1 = min(y0 + 1, HH - 1) - by * 16;

            uint4 v[4];
            v[0] = sreg[(sy0 * 17 + sx0) * 8 + c8];
            v[1] = sreg[(sy0 * 17 + sx1) * 8 + c8];
            v[2] = sreg[(sy1 * 17 + sx0) * 8 + c8];
            v[3] = sreg[(sy1 * 17 + sx1) * 8 + c8];

            float acc[8] = {0};
            accum(v, w, acc);
            store_h8(dst, p, c8, acc);
        }
    }
}

// ---------------------------------------------------------------------------
// Pass2 block (unchanged from best): random gathers + smem-staged NCHW out.
// ---------------------------------------------------------------------------
__device__ __forceinline__ void load4(const uint4* __restrict__ src,
                                      int x0, int y0, int c8, uint4* v) {
    const int xc0 = min(max(x0, 0), WW - 1);
    const int xc1 = min(x0 + 1, WW - 1);
    const int yc0 = min(max(y0, 0), HH - 1);
    const int yc1 = min(y0 + 1, HH - 1);
    v[0] = src[(((yc0 << 8) + xc0) << 3) + c8];
    v[1] = src[(((yc0 << 8) + xc1) << 3) + c8];
    v[2] = src[(((yc1 << 8) + xc0) << 3) + c8];
    v[3] = src[(((yc1 << 8) + xc1) << 3) + c8];
}

__device__ __forceinline__ void pass2_block(const float* __restrict__ grid,
                                            float* __restrict__ out,
                                            int n, int blk,
                                            float* __restrict__ smf /*64*65*/) {
    const int t  = threadIdx.x;
    const int c8 = t & 7;
    const int px = t >> 3;
    const int p0 = blk * 64;
    const int pA = p0 + px;
    const int pB = pA + 32;

    const float2 gA = ((const float2*)grid)[(size_t)n * PP + pA];
    const float2 gB = ((const float2*)grid)[(size_t)n * PP + pB];
    int xA, yA, xB, yB; float fxA, fyA, fxB, fyB;
    bl_setup(gA.x, gA.y, xA, yA, fxA, fyA);
    bl_setup(gB.x, gB.y, xB, yB, fxB, fyB);

    const uint4* src = (const uint4*)g_first[n & 1];
    uint4 va[4], vb[4];
    load4(src, xA, yA, c8, va);
    load4(src, xB, yB, c8, vb);

    float wA[4], wB[4];
    bl_weights(xA, yA, fxA, fyA, wA);
    bl_weights(xB, yB, fxB, fyB, wB);

    float accA[8] = {0}, accB[8] = {0};
    accum(va, wA, accA);
    accum(vb, wB, accB);

    #pragma unroll
    for (int k = 0; k < 8; k++) {
        smf[(c8 * 8 + k) * 65 + px]      = accA[k];
        smf[(c8 * 8 + k) * 65 + px + 32] = accB[k];
    }
    __syncthreads();

    const int w = t >> 5, lane = t & 31;
    #pragma unroll
    for (int k = 0; k < 8; k++) {
        const int cc = w * 8 + k;
        const size_t ob = (((size_t)n * CH + cc) << 16) + p0;
        out[ob + lane]      = smf[cc * 65 + lane];
        out[ob + 32 + lane] = smf[cc * 65 + 32 + lane];
    }
}

// ---------------------------------------------------------------------------
// Sort chain (all batches, grid-only dependency). Every kernel grid-dep-syncs
// so completion is transitive down the PDL chain.
// ---------------------------------------------------------------------------
__global__ void k_sinit() {
    cudaTriggerProgrammaticLaunchCompletion();
    const int t = threadIdx.x;
    for (int i = t; i < NB * 256; i += 256) {
        ((int*)g_hist)[i] = 0;
        ((int*)g_cur)[i] = 0;
    }
}

__global__ void k_hist(const float* __restrict__ grid) {
    cudaTriggerProgrammaticLaunchCompletion();
    cudaGridDependencySynchronize();
    __shared__ int h[256];
    const int t = threadIdx.x;
    const int n = blockIdx.x >> 6;
    const int seg = blockIdx.x & 63;
    h[t] = 0;
    __syncthreads();
    #pragma unroll
    for (int i = 0; i < 4; i++) {
        const int p = seg * 1024 + i * 256 + t;
        atomicAdd(&h[pixel_bin(((const float2*)grid)[(size_t)n * PP + p])], 1);
    }
    __syncthreads();
    if (h[t]) atomicAdd(&g_hist[n][t], h[t]);
}

__global__ void k_scan() {
    cudaTriggerProgrammaticLaunchCompletion();
    cudaGridDependencySynchronize();
    __shared__ int s[256];
    const int t = threadIdx.x, n = blockIdx.x;
    s[t] = g_hist[n][t];
    __syncthreads();
    #pragma unroll
    for (int off = 1; off < 256; off <<= 1) {
        int v = (t >= off) ? s[t - off] : 0;
        __syncthreads();
        s[t] += v;
        __syncthreads();
    }
    if (t == 0) g_bstart[n][0] = 0;
    g_bstart[n][t + 1] = s[t];
}

__global__ void k_scatter(const float* __restrict__ grid) {
    cudaTriggerProgrammaticLaunchCompletion();
    cudaGridDependencySynchronize();
    const int t = threadIdx.x;
    const int n = blockIdx.x >> 6;
    const int seg = blockIdx.x & 63;
    #pragma unroll
    for (int i = 0; i < 4; i++) {
        const int p = seg * 1024 + i * 256 + t;
        const int bin = pixel_bin(((const float2*)grid)[(size_t)n * PP + p]);
        const int slot = atomicAdd(&g_cur[n][bin], 1);
        g_sidx[n][g_bstart[n][bin] + slot] = p;
    }
}

// ---------------------------------------------------------------------------
// Prologue: transpose batches 0 and 1. Syncs scatter-complete first so the
// downstream chain's completion transitivity covers the sort results.
// ---------------------------------------------------------------------------
__global__ void __launch_bounds__(256, 5)
k_transpose01(const float* __restrict__ feat) {
    cudaTriggerProgrammaticLaunchCompletion();
    cudaGridDependencySynchronize();
    __shared__ float sm[64 * 65];
    transpose_tile(feat, blockIdx.x >> 10, blockIdx.x & 1023, sm);
}

// Fused A(m): blocks [0,1024) = transpose batch m+2 (sync-free tail filler);
//             blocks [1024,1536) = binned pass1 for batches m, m+1 (synced).
__global__ void __launch_bounds__(256, 5)
k_fusedA(const float* __restrict__ feat, const float* __restrict__ grid, int m) {
    cudaTriggerProgrammaticLaunchCompletion();
    __shared__ __align__(16) uint4 sreg[17 * 17 * 8];   // 36992B
    if (blockIdx.x < 1024) {
        if (m + 2 < NB)
            transpose_tile(feat, m + 2, blockIdx.x, (float*)sreg);
    } else {
        cudaGridDependencySynchronize();   // predecessor complete (transitive)
        const int q = blockIdx.x - 1024;
        pass1_bin_block(grid, m + (q >> 8), q & 255, sreg);
    }
}

// Fused B(m): blocks [0,1024) = transpose batch m+3 (sync-free tail filler);
//             blocks [1024,3072) = pass2 for batches m and m+1 (synced).
__global__ void __launch_bounds__(256, 5)
k_fusedB(const float* __restrict__ feat, const float* __restrict__ grid,
         float* __restrict__ out, int m) {
    cudaTriggerProgrammaticLaunchCompletion();
    __shared__ float sm[64 * 65];
    if (blockIdx.x < 1024) {
        if (m + 3 < NB)
            transpose_tile(feat, m + 3, blockIdx.x, sm);
    } else {
        cudaGridDependencySynchronize();   // wait A(m) (pass1 results)
        const int b = blockIdx.x - 1024;
        pass2_block(grid, out, m + (b >> 10), b & 1023, sm);
    }
}

// ---------------------------------------------------------------------------
static inline void launch_pdl(void* func, dim3 grid, void** args) {
    cudaLaunchConfig_t cfg = {};
    cfg.gridDim = grid;
    cfg.blockDim = dim3(256, 1, 1);
    cfg.dynamicSmemBytes = 0;
    cfg.stream = 0;
    cudaLaunchAttribute attr[1];
    attr[0].id = cudaLaunchAttributeProgrammaticStreamSerialization;
    attr[0].val.programmaticStreamSerializationAllowed = 1;
    cfg.attrs = attr;
    cfg.numAttrs = 1;
    cudaLaunchKernelExC(&cfg, func, args);
}

extern "C" void kernel_launch(void* const* d_in, const int* in_sizes, int n_in,
                              void* d_out, int out_size) {
    const float* feature = (const float*)d_in[0];
    const float* grid    = (const float*)d_in[1];
    float*       out     = (float*)d_out;

    k_sinit<<<1, 256>>>();
    {
        void* a[] = {(void*)&grid};
        launch_pdl((void*)k_hist, dim3(NB * 64), a);
    }
    launch_pdl((void*)k_scan, dim3(NB), nullptr);
    {
        void* a[] = {(void*)&grid};
        launch_pdl((void*)k_scatter, dim3(NB * 64), a);
    }
    {
        void* a[] = {(void*)&feature};
        launch_pdl((void*)k_transpose01, dim3(2048), a);
    }
    for (int m = 0; m < NB; m += 2) {
        {
            void* a[] = {(void*)&feature, (void*)&grid, (void*)&m};
            launch_pdl((void*)k_fusedA, dim3(1024 + 512), a);
        }
        {
            void* a[] = {(void*)&feature, (void*)&grid, (void*)&out, (void*)&m};
            launch_pdl((void*)k_fusedB, dim3(3072), a);
        }
    }
}

// round 17
// speedup vs baseline: 1.6893x; 1.6893x over previous
#include <cuda_runtime.h>
#include <cuda_fp16.h>
#include <cstdint>

#define NB 8
#define CH 64
#define HH 256
#define WW 256
#define PP (HH*WW)   // 65536 pixels per batch

// fp16 scratch: 8-deep NHWC feature ring (8x8MB=64MB) + 2-deep NHWC
// intermediate (2x8MB). Hot working set ~40MB -> L2-resident (126MB L2).
__device__ __half g_fN[8][(size_t)PP * CH];
__device__ __half g_first[2][(size_t)PP * CH];

// ---------------------------------------------------------------------------
// Transpose one 64ch x 64px tile of batch n: fp32 NCHW -> fp16 NHWC.
// Feature is read once -> streaming loads (__ldcs) to avoid L2 pollution.
// ---------------------------------------------------------------------------
__device__ __forceinline__ void transpose_tile(const float* __restrict__ feat,
                                               int n, int tile,
                                               float* __restrict__ sm /*64*65*/) {
    const int pbase = tile * 64;
    const int t = threadIdx.x;
    const float* src = feat + (size_t)n * CH * PP;

    const int px4 = (t & 15) * 4;   // pixel offset 0..60
    const int c0  = t >> 4;         // 0..15
    #pragma unroll
    for (int i = 0; i < 4; i++) {
        const int c = c0 + i * 16;
        const float4 v = __ldcs((const float4*)(src + (size_t)c * PP + pbase + px4));
        sm[c * 65 + px4 + 0] = v.x;
        sm[c * 65 + px4 + 1] = v.y;
        sm[c * 65 + px4 + 2] = v.z;
        sm[c * 65 + px4 + 3] = v.w;
    }
    __syncthreads();

    __half* dst = g_fN[n & 7];
    const int c8  = t & 7;          // 8-channel chunk
    const int px0 = t >> 3;         // 0..31
    #pragma unroll
    for (int i = 0; i < 2; i++) {
        const int px = px0 + 32 * i;
        __half2 h[4];
        #pragma unroll
        for (int k = 0; k < 4; k++) {
            float2 f = make_float2(sm[(c8 * 8 + 2 * k) * 65 + px],
                                   sm[(c8 * 8 + 2 * k + 1) * 65 + px]);
            h[k] = __float22half2_rn(f);
        }
        ((uint4*)(dst + (size_t)(pbase + px) * 64))[c8] = *(uint4*)h;
    }
}

// ---------------------------------------------------------------------------
// Bilinear helpers (fp32 math; zeros padding folded into weights)
// ---------------------------------------------------------------------------
__device__ __forceinline__ void bl_setup(float gx, float gy,
                                         int& x0, int& y0, float& fx, float& fy) {
    float ix = ((gx + 1.0f) * (float)WW - 1.0f) * 0.5f;
    float iy = ((gy + 1.0f) * (float)HH - 1.0f) * 0.5f;
    float fx0 = floorf(ix);
    float fy0 = floorf(iy);
    fx = ix - fx0;
    fy = iy - fy0;
    x0 = (int)fx0;
    y0 = (int)fy0;
}

// Unconditional loads from clamped (always in-bounds) corner addresses.
__device__ __forceinline__ void load4(const uint4* __restrict__ src,
                                      int x0, int y0, int c8, uint4* v) {
    const int xc0 = min(max(x0, 0), WW - 1);
    const int xc1 = min(x0 + 1, WW - 1);       // x0+1 >= 0 always
    const int yc0 = min(max(y0, 0), HH - 1);
    const int yc1 = min(y0 + 1, HH - 1);
    v[0] = src[(((yc0 << 8) + xc0) << 3) + c8];
    v[1] = src[(((yc0 << 8) + xc1) << 3) + c8];
    v[2] = src[(((yc1 << 8) + xc0) << 3) + c8];
    v[3] = src[(((yc1 << 8) + xc1) << 3) + c8];
}

// Bilinear weights with validity folded in (invalid corner -> weight 0,
// exactly matching padding_mode='zeros').
__device__ __forceinline__ void bl_weights(int x0, int y0, float fx, float fy,
                                           float* w /*4*/) {
    const float vx0 = (x0 >= 0) ? 1.0f : 0.0f;
    const float vx1 = (x0 + 1 < WW) ? 1.0f : 0.0f;
    const float vy0 = (y0 >= 0) ? 1.0f : 0.0f;
    const float vy1 = (y0 + 1 < HH) ? 1.0f : 0.0f;
    const float ax0 = (1.0f - fx) * vx0, ax1 = fx * vx1;
    const float ay0 = (1.0f - fy) * vy0, ay1 = fy * vy1;
    w[0] = ax0 * ay0; w[1] = ax1 * ay0; w[2] = ax0 * ay1; w[3] = ax1 * ay1;
}

// Weighted accumulate of 4 corner uint4s into 8 fp32 channels, using
// packed f32x2 FMA (Blackwell FFMA2; ptxas never auto-fuses, PTX-only).
__device__ __forceinline__ void accum(const uint4* v, const float* w,
                                      float* acc) {
    unsigned long long ap[4];
    #pragma unroll
    for (int k = 0; k < 4; k++)
        asm("mov.b64 %0, {%1,%2};" : "=l"(ap[k]) : "f"(acc[2*k]), "f"(acc[2*k+1]));
    #pragma unroll
    for (int j = 0; j < 4; j++) {
        unsigned long long wp;
        asm("mov.b64 %0, {%1,%1};" : "=l"(wp) : "f"(w[j]));
        const __half2* h = (const __half2*)&v[j];
        #pragma unroll
        for (int k = 0; k < 4; k++) {
            float2 f = __half22float2(h[k]);
            unsigned long long fp;
            asm("mov.b64 %0, {%1,%2};" : "=l"(fp) : "f"(f.x), "f"(f.y));
            asm("fma.rn.f32x2 %0, %1, %2, %0;" : "+l"(ap[k]) : "l"(fp), "l"(wp));
        }
    }
    #pragma unroll
    for (int k = 0; k < 4; k++)
        asm("mov.b64 {%0,%1}, %2;" : "=f"(acc[2*k]), "=f"(acc[2*k+1]) : "l"(ap[k]));
}

__device__ __forceinline__ void store_h8(__half* __restrict__ dst, int p, int c8,
                                         const float* acc) {
    __half2 h[4];
    #pragma unroll
    for (int k = 0; k < 4; k++)
        h[k] = __float22half2_rn(make_float2(acc[2 * k], acc[2 * k + 1]));
    ((uint4*)(dst + (size_t)p * 64))[c8] = *(uint4*)h;
}

// ---------------------------------------------------------------------------
// Pass1 block: 64 pixels x 64 channels, 256 threads, 2 pixels/thread.
// ---------------------------------------------------------------------------
__device__ __forceinline__ void pass1_block(const float* __restrict__ grid,
                                            int n, int blk) {
    const int t  = threadIdx.x;
    const int c8 = t & 7;
    const int px = t >> 3;
    const int pA = blk * 64 + px;
    const int pB = pA + 32;

    const float2 gA = ((const float2*)grid)[(size_t)n * PP + pA];
    const float2 gB = ((const float2*)grid)[(size_t)n * PP + pB];
    int xA, yA, xB, yB; float fxA, fyA, fxB, fyB;
    bl_setup(gA.x, gA.y, xA, yA, fxA, fyA);
    bl_setup(gB.x, gB.y, xB, yB, fxB, fyB);

    const uint4* src = (const uint4*)g_fN[n & 7];
    uint4 va[4], vb[4];
    load4(src, xA, yA, c8, va);
    load4(src, xB, yB, c8, vb);

    float wA[4], wB[4];
    bl_weights(xA, yA, fxA, fyA, wA);
    bl_weights(xB, yB, fxB, fyB, wB);

    float accA[8] = {0}, accB[8] = {0};
    accum(va, wA, accA);
    accum(vb, wB, accB);

    __half* dst = g_first[n & 1];
    store_h8(dst, pA, c8, accA);
    store_h8(dst, pB, c8, accB);
}

// ---------------------------------------------------------------------------
// Pass2 block: 64 pixels x 64 channels, 256 threads; smem-staged NCHW output
// written with streaming stores (__stcs) to keep scratch L2-resident.
// ---------------------------------------------------------------------------
__device__ __forceinline__ void pass2_block(const float* __restrict__ grid,
                                            float* __restrict__ out,
                                            int n, int blk,
                                            float* __restrict__ smf /*64*65*/) {
    const int t  = threadIdx.x;
    const int c8 = t & 7;
    const int px = t >> 3;
    const int p0 = blk * 64;
    const int pA = p0 + px;
    const int pB = pA + 32;

    const float2 gA = ((const float2*)grid)[(size_t)n * PP + pA];
    const float2 gB = ((const float2*)grid)[(size_t)n * PP + pB];
    int xA, yA, xB, yB; float fxA, fyA, fxB, fyB;
    bl_setup(gA.x, gA.y, xA, yA, fxA, fyA);
    bl_setup(gB.x, gB.y, xB, yB, fxB, fyB);

    const uint4* src = (const uint4*)g_first[n & 1];
    uint4 va[4], vb[4];
    load4(src, xA, yA, c8, va);
    load4(src, xB, yB, c8, vb);

    float wA[4], wB[4];
    bl_weights(xA, yA, fxA, fyA, wA);
    bl_weights(xB, yB, fxB, fyB, wB);

    float accA[8] = {0}, accB[8] = {0};
    accum(va, wA, accA);
    accum(vb, wB, accB);

    #pragma unroll
    for (int k = 0; k < 8; k++) {
        smf[(c8 * 8 + k) * 65 + px]      = accA[k];
        smf[(c8 * 8 + k) * 65 + px + 32] = accB[k];
    }
    __syncthreads();

    const int w = t >> 5, lane = t & 31;     // 8 warps x 8 channels each
    #pragma unroll
    for (int k = 0; k < 8; k++) {
        const int cc = w * 8 + k;
        const size_t ob = (((size_t)n * CH + cc) << 16) + p0;
        __stcs(&out[ob + lane],      smf[cc * 65 + lane]);
        __stcs(&out[ob + 32 + lane], smf[cc * 65 + 32 + lane]);
    }
}

// ---------------------------------------------------------------------------
// Prologue: transpose batches 0 and 1 (2048 tiles). Launched without PDL.
// ---------------------------------------------------------------------------
__global__ void __launch_bounds__(256, 6)
k_transpose01(const float* __restrict__ feat) {
    cudaTriggerProgrammaticLaunchCompletion();
    __shared__ float sm[64 * 65];
    transpose_tile(feat, blockIdx.x >> 10, blockIdx.x & 1023, sm);
}

// Fused A(m): blocks [0,1024) = transpose batch m+2 (sync-free tail filler);
//             blocks [1024, 3072) = pass1 for batches m and m+1 (synced).
__global__ void __launch_bounds__(256, 6)
k_fusedA(const float* __restrict__ feat, const float* __restrict__ grid, int m) {
    cudaTriggerProgrammaticLaunchCompletion();
    __shared__ float sm[64 * 65];
    if (blockIdx.x < 1024) {
        if (m + 2 < NB)
            transpose_tile(feat, m + 2, blockIdx.x, sm);
    } else {
        cudaGridDependencySynchronize();   // wait predecessor (prologue / B(m-2))
        const int b = blockIdx.x - 1024;
        pass1_block(grid, m + (b >> 10), b & 1023);
    }
}

// Fused B(m): blocks [0,1024) = transpose batch m+3 (sync-free tail filler);
//             blocks [1024, 3072) = pass2 for batches m and m+1 (synced).
__global__ void __launch_bounds__(256, 6)
k_fusedB(const float* __restrict__ feat, const float* __restrict__ grid,
         float* __restrict__ out, int m) {
    cudaTriggerProgrammaticLaunchCompletion();
    __shared__ float sm[64 * 65];
    if (blockIdx.x < 1024) {
        if (m + 3 < NB)
            transpose_tile(feat, m + 3, blockIdx.x, sm);
    } else {
        cudaGridDependencySynchronize();   // wait A(m) (pass1 results)
        const int b = blockIdx.x - 1024;
        pass2_block(grid, out, m + (b >> 10), b & 1023, sm);
    }
}

// ---------------------------------------------------------------------------
static inline void launch_pdl(void* func, dim3 grid, void** args) {
    cudaLaunchConfig_t cfg = {};
    cfg.gridDim = grid;
    cfg.blockDim = dim3(256, 1, 1);
    cfg.dynamicSmemBytes = 0;
    cfg.stream = 0;
    cudaLaunchAttribute attr[1];
    attr[0].id = cudaLaunchAttributeProgrammaticStreamSerialization;
    attr[0].val.programmaticStreamSerializationAllowed = 1;
    cfg.attrs = attr;
    cfg.numAttrs = 1;
    cudaLaunchKernelExC(&cfg, func, args);
}

extern "C" void kernel_launch(void* const* d_in, const int* in_sizes, int n_in,
                              void* d_out, int out_size) {
    const float* feature = (const float*)d_in[0];
    const float* grid    = (const float*)d_in[1];
    float*       out     = (float*)d_out;

    k_transpose01<<<2048, 256>>>(feature);
    for (int m = 0; m < NB; m += 2) {
        {
            void* args[] = {(void*)&feature, (void*)&grid, (void*)&m};
            launch_pdl((void*)k_fusedA, dim3(3072), args);
        }
        {
            void* args[] = {(void*)&feature, (void*)&grid, (void*)&out, (void*)&m};
            launch_pdl((void*)k_fusedB, dim3(3072), args);
        }
    }
}